// round 17
// baseline (speedup 1.0000x reference)
#include <cuda_runtime.h>
#include <cuda_bf16.h>
#include <math.h>
#include <stdint.h>

#define B 32
#define L 256
#define D 512
#define MAX_LEN 2048                     // L * MAX_DUR(8)
#define ROWS_PB 32                       // output rows per block
#define BLOCKS_PER_BATCH (MAX_LEN / ROWS_PB)   // 64
#define F4_PER_ROW (D / 4)               // 128
#define CHUNK_ROWS 8                     // rows per TMA bulk store (16 KB)
#define CHUNK_F4 (CHUNK_ROWS * F4_PER_ROW)     // 1024 float4
#define NCHUNK (ROWS_PB / CHUNK_ROWS)    // 4
#define CHUNK_BYTES (CHUNK_F4 * 16)      // 16384

// ---------------------------------------------------------------------------
// Fused length-regulator — TMA bulk-store probe.
// Scan + index derivation identical to the 24.9us champion. The write path
// is replaced: threads gather 8 output rows into a 16KB SMEM buffer, then a
// single thread issues cp.async.bulk (SMEM -> GMEM) with an L2 evict_first
// cache hint (preserving the streaming-store semantics the graph-replay
// steady state requires). Two buffers ping-pong; wait_group 1 recycles.
// This moves the 134MB write stream off the per-thread STG/L1tex path onto
// the TMA engine. Grid = 2048 blocks x 256 threads.
// ---------------------------------------------------------------------------
__global__ void __launch_bounds__(256)
lr_fused_kernel(const float* __restrict__ att_out,
                const float* __restrict__ duration,
                const void*  __restrict__ alpha_ptr,
                float* __restrict__ out)
{
    const int b        = blockIdx.x / BLOCKS_PER_BATCH;
    const int row_base = (blockIdx.x % BLOCKS_PER_BATCH) * ROWS_PB;
    const int t    = threadIdx.x;       // 0..255
    const int lane = t & 31;
    const int wid  = t >> 5;            // 0..7

    // --- resolve alpha (int32 or float32, bit-sniffed) ---
    int   ab = *(const int*)alpha_ptr;
    float af = __int_as_float(ab);
    float alpha = (fabsf(af) >= 1e-30f && fabsf(af) <= 1e30f) ? af : (float)ab;

    // --- round (rintf = round-half-even, matches jnp.round) ---
    int r = (int)rintf(__ldg(&duration[b * L + t]) * alpha);

    // --- inclusive scan over 256 values ---
    int v = r;
    #pragma unroll
    for (int off = 1; off < 32; off <<= 1) {
        int n = __shfl_up_sync(0xffffffffu, v, off);
        if (lane >= off) v += n;
    }
    __shared__ int warp_tot[8];
    __shared__ int warp_pre[8];
    if (lane == 31) warp_tot[wid] = v;
    __syncthreads();
    if (t < 8) {
        int wv = warp_tot[t];
        #pragma unroll
        for (int off = 1; off < 8; off <<= 1) {
            int n = __shfl_up_sync(0xffu, wv, off);
            if (t >= off) wv += n;
        }
        warp_pre[t] = wv;
    }
    __syncthreads();
    int csum = v + (wid > 0 ? warp_pre[wid - 1] : 0);

    __shared__ int s_csum[L];
    s_csum[t] = csum;
    __syncthreads();

    const int total = s_csum[L - 1];

    // --- per-row source index for this block's 32 rows (-1 = masked) ---
    __shared__ int s_idx[ROWS_PB];
    if (t < ROWS_PB) {
        int pos = row_base + t;
        int outi;
        if (pos >= total) {
            outi = -1;
        } else {
            int lo = 0, hi = L;             // first i with csum[i] > pos
            while (lo < hi) {
                int mid = (lo + hi) >> 1;
                if (s_csum[mid] > pos) hi = mid; else lo = mid + 1;
            }
            outi = lo < (L - 1) ? lo : (L - 1);
        }
        s_idx[t] = outi;
    }
    __syncthreads();

    // --- gather into SMEM, drain via TMA bulk stores (ping-pong) ---
    __shared__ float4 sbuf[2][CHUNK_F4];    // 2 x 16 KB

    const int rl  = t >> 7;                 // 0/1
    const int col = t & (F4_PER_ROW - 1);   // float4 column (constant)

    const float4* __restrict__ src =
        (const float4*)(att_out + (size_t)b * L * D) + col;
    float* __restrict__ dstf = out + ((size_t)b * MAX_LEN + row_base) * D;
    const float4 zero = make_float4(0.f, 0.f, 0.f, 0.f);

    // streaming-equivalent L2 policy for the bulk stores
    unsigned long long pol;
    asm volatile("createpolicy.fractional.L2::evict_first.b64 %0, 1.0;"
                 : "=l"(pol));

    #pragma unroll
    for (int c = 0; c < NCHUNK; c++) {
        if (c >= 2) {
            // recycle buffer (c&1): group issued at c-2 must be complete
            if (t == 0)
                asm volatile("cp.async.bulk.wait_group 1;" ::: "memory");
            __syncthreads();
        }
        float4* bufp = sbuf[c & 1];
        #pragma unroll
        for (int k = 0; k < 4; k++) {
            int row = CHUNK_ROWS * c + 2 * k + rl;   // warp-uniform
            int idx = s_idx[row];
            float4 val = (idx >= 0)
                       ? __ldg(src + (size_t)idx * F4_PER_ROW)
                       : zero;
            bufp[k * 256 + t] = val;
        }
        __syncthreads();
        if (t == 0) {
            unsigned int saddr =
                (unsigned int)__cvta_generic_to_shared(bufp);
            float* dchunk = dstf + (size_t)c * CHUNK_ROWS * D;
            asm volatile("fence.proxy.async.shared::cta;" ::: "memory");
            asm volatile(
                "cp.async.bulk.global.shared::cta.bulk_group.L2::cache_hint "
                "[%0], [%1], %2, %3;"
                :: "l"(dchunk), "r"(saddr), "r"((unsigned int)CHUNK_BYTES),
                   "l"(pol)
                : "memory");
            asm volatile("cp.async.bulk.commit_group;" ::: "memory");
        }
    }
    // all bulk stores must complete before SMEM is released at block exit
    if (t == 0)
        asm volatile("cp.async.bulk.wait_group 0;" ::: "memory");
}

extern "C" void kernel_launch(void* const* d_in, const int* in_sizes, int n_in,
                              void* d_out, int out_size)
{
    const float* att_out  = (const float*)d_in[0];
    const float* duration = (const float*)d_in[1];
    const void*  alpha    = d_in[2];

    lr_fused_kernel<<<B * BLOCKS_PER_BATCH, 256>>>(att_out, duration, alpha,
                                                   (float*)d_out);
}